// round 4
// baseline (speedup 1.0000x reference)
#include <cuda_runtime.h>

#define BB 32
#define TT 2048
#define DD 512
#define D4 128
#define NSLOT 64
#define NBLK (BB * NSLOT)    // 2048 blocks
#define TSTRIDE (2 * NSLOT)  // 128 rows between a thread's iterations

// Scratch: zero-initialized at module load; finalizing block re-zeros after
// consuming, so every invocation (incl. graph replays) sees zeroed scratch.
__device__ float    g_sumdiff[BB * DD];
__device__ float    g_wl;
__device__ unsigned g_count;   // self-wrapping ticket via atomicInc

__device__ __forceinline__ float smooth_l1(float d) {
    float ad = fabsf(d);
    return (ad < 1.0f) ? 0.5f * d * d : ad - 0.5f;
}

__global__ __launch_bounds__(256) void fused_kernel(
    const float* __restrict__ preds,
    const float* __restrict__ targets,
    const int* __restrict__ lens,
    float* __restrict__ out)
{
    const int b    = blockIdx.x >> 6;          // / NSLOT
    const int slot = blockIdx.x & (NSLOT - 1);
    const int len  = lens[b];

    const int d4 = threadIdx.x & 127;          // float4 lane in D
    const int th = threadIdx.x >> 7;           // 2 t-rows in flight per block

    const float4* __restrict__ p4 = (const float4*)(preds   + (size_t)b * TT * DD);
    const float4* __restrict__ q4 = (const float4*)(targets + (size_t)b * TT * DD);

    float sdx = 0.f, sdy = 0.f, sdz = 0.f, sdw = 0.f;
    float wl = 0.f;

    int t = slot * 2 + th;

    // unrolled by 4: 8 independent volatile LDG.128 front-batched per iteration
    // (.cv path — the documented route to the full-chip LTS throughput cap)
    for (; t + 3 * TSTRIDE < len; t += 4 * TSTRIDE) {
        float4 p0 = __ldcv(&p4[(size_t)(t              ) * D4 + d4]);
        float4 p1 = __ldcv(&p4[(size_t)(t +     TSTRIDE) * D4 + d4]);
        float4 p2 = __ldcv(&p4[(size_t)(t + 2 * TSTRIDE) * D4 + d4]);
        float4 p3 = __ldcv(&p4[(size_t)(t + 3 * TSTRIDE) * D4 + d4]);
        float4 q0 = __ldcv(&q4[(size_t)(t              ) * D4 + d4]);
        float4 q1 = __ldcv(&q4[(size_t)(t +     TSTRIDE) * D4 + d4]);
        float4 q2 = __ldcv(&q4[(size_t)(t + 2 * TSTRIDE) * D4 + d4]);
        float4 q3 = __ldcv(&q4[(size_t)(t + 3 * TSTRIDE) * D4 + d4]);

        float dx, dy, dz, dw;
        dx = p0.x - q0.x; dy = p0.y - q0.y; dz = p0.z - q0.z; dw = p0.w - q0.w;
        sdx += dx; sdy += dy; sdz += dz; sdw += dw;
        wl += smooth_l1(dx) + smooth_l1(dy) + smooth_l1(dz) + smooth_l1(dw);
        dx = p1.x - q1.x; dy = p1.y - q1.y; dz = p1.z - q1.z; dw = p1.w - q1.w;
        sdx += dx; sdy += dy; sdz += dz; sdw += dw;
        wl += smooth_l1(dx) + smooth_l1(dy) + smooth_l1(dz) + smooth_l1(dw);
        dx = p2.x - q2.x; dy = p2.y - q2.y; dz = p2.z - q2.z; dw = p2.w - q2.w;
        sdx += dx; sdy += dy; sdz += dz; sdw += dw;
        wl += smooth_l1(dx) + smooth_l1(dy) + smooth_l1(dz) + smooth_l1(dw);
        dx = p3.x - q3.x; dy = p3.y - q3.y; dz = p3.z - q3.z; dw = p3.w - q3.w;
        sdx += dx; sdy += dy; sdz += dz; sdw += dw;
        wl += smooth_l1(dx) + smooth_l1(dy) + smooth_l1(dz) + smooth_l1(dw);
    }
    for (; t < len; t += TSTRIDE) {
        float4 p = __ldcv(&p4[(size_t)t * D4 + d4]);
        float4 q = __ldcv(&q4[(size_t)t * D4 + d4]);
        float dx = p.x - q.x, dy = p.y - q.y, dz = p.z - q.z, dw = p.w - q.w;
        sdx += dx; sdy += dy; sdz += dz; sdw += dw;
        wl += smooth_l1(dx) + smooth_l1(dy) + smooth_l1(dz) + smooth_l1(dw);
    }

    // combine the two t-halves in shared, then one set of atomics (half as many)
    __shared__ float s_half[D4 * 4];
    if (th == 1) {
        s_half[d4 * 4 + 0] = sdx; s_half[d4 * 4 + 1] = sdy;
        s_half[d4 * 4 + 2] = sdz; s_half[d4 * 4 + 3] = sdw;
    }
    __syncthreads();
    if (th == 0) {
        const int base = b * DD + d4 * 4;
        atomicAdd(&g_sumdiff[base + 0], sdx + s_half[d4 * 4 + 0]);
        atomicAdd(&g_sumdiff[base + 1], sdy + s_half[d4 * 4 + 1]);
        atomicAdd(&g_sumdiff[base + 2], sdz + s_half[d4 * 4 + 2]);
        atomicAdd(&g_sumdiff[base + 3], sdw + s_half[d4 * 4 + 3]);
    }

    // word-loss partial: block reduce, one atomic per block
    __shared__ float s_wl[256];
    s_wl[threadIdx.x] = wl;
    __syncthreads();
#pragma unroll
    for (int s = 128; s > 0; s >>= 1) {
        if (threadIdx.x < s) s_wl[threadIdx.x] += s_wl[threadIdx.x + s];
        __syncthreads();
    }

    __shared__ bool s_last;
    if (threadIdx.x == 0) {
        atomicAdd(&g_wl, s_wl[0]);
        __threadfence();                              // release partials
        unsigned old = atomicInc(&g_count, NBLK - 1); // wraps to 0 after NBLK
        s_last = (old == NBLK - 1);
    }
    __syncthreads();
    if (!s_last) return;

    // ---- last block: finalize ----
    __threadfence();                                  // acquire all partials
    const int tid = threadIdx.x;

    __shared__ float s_len[BB];
    __shared__ float s_sumlen;
    if (tid < BB) s_len[tid] = (float)lens[tid];
    __syncthreads();
    if (tid == 0) {
        float s = 0.f;
#pragma unroll
        for (int b2 = 0; b2 < BB; b2++) s += s_len[b2];
        s_sumlen = s;
    }

    float acc = 0.f;
#pragma unroll
    for (int b2 = 0; b2 < BB; b2++) {
        float inv = 1.0f / s_len[b2];
        float m0 = g_sumdiff[b2 * DD + tid]       * inv;
        float m1 = g_sumdiff[b2 * DD + tid + 256] * inv;
        acc += smooth_l1(m0) + smooth_l1(m1);
        g_sumdiff[b2 * DD + tid]       = 0.f;     // re-zero for next invocation
        g_sumdiff[b2 * DD + tid + 256] = 0.f;
    }

    __shared__ float s_red[256];
    s_red[tid] = acc;
    __syncthreads();
#pragma unroll
    for (int s = 128; s > 0; s >>= 1) {
        if (tid < s) s_red[tid] += s_red[tid + s];
        __syncthreads();
    }

    if (tid == 0) {
        float sentence = s_red[0] / (float)DD;                 // sum_b mean_d
        float word     = g_wl / (s_sumlen * (float)DD);
        out[0] = word + sentence / (float)BB;
        g_wl = 0.f;                                            // re-zero
    }
}

extern "C" void kernel_launch(void* const* d_in, const int* in_sizes, int n_in,
                              void* d_out, int out_size)
{
    const float* preds   = (const float*)d_in[0];
    const float* targets = (const float*)d_in[1];
    const int*   lens    = (const int*)d_in[2];
    float*       out     = (float*)d_out;

    fused_kernel<<<NBLK, 256>>>(preds, targets, lens, out);
}

// round 5
// speedup vs baseline: 1.1542x; 1.1542x over previous
#include <cuda_runtime.h>

#define BB 32
#define TT 2048
#define DD 512
#define D4 128
#define NTILE 64
#define TILE 32              // rows per tile (contiguous)
#define NBLK (BB * NTILE)    // 2048 blocks

// Scratch: zero-initialized at module load; finalizing block re-zeros after
// consuming, so every invocation (incl. graph replays) sees zeroed scratch.
__device__ float    g_sumdiff[BB * DD];
__device__ float    g_wl;
__device__ unsigned g_count;   // self-wrapping ticket via atomicInc

__device__ __forceinline__ float smooth_l1(float d) {
    float ad = fabsf(d);
    return (ad < 1.0f) ? 0.5f * d * d : ad - 0.5f;
}

__global__ __launch_bounds__(256) void fused_kernel(
    const float* __restrict__ preds,
    const float* __restrict__ targets,
    const int* __restrict__ lens,
    float* __restrict__ out)
{
    const int b    = blockIdx.x >> 6;          // / NTILE
    const int tile = blockIdx.x & (NTILE - 1);
    const int len  = lens[b];
    const int t0   = tile * TILE;

    const int d4 = threadIdx.x & 127;          // float4 lane in D
    const int th = threadIdx.x >> 7;           // 2 consecutive t-rows in flight

    if (t0 < len) {                            // tile has valid rows
        const int tend = min(t0 + TILE, len);

        const float4* __restrict__ p4 = (const float4*)(preds   + (size_t)b * TT * DD);
        const float4* __restrict__ q4 = (const float4*)(targets + (size_t)b * TT * DD);

        float sdx = 0.f, sdy = 0.f, sdz = 0.f, sdw = 0.f;
        float wl = 0.f;

        int t = t0 + th;
        // unrolled by 4 along consecutive rows: 8 independent LDG.128,
        // addresses 4KB apart -> block streams a contiguous 64KB span
        for (; t + 6 < tend; t += 8) {
            float4 p0 = p4[(size_t)(t    ) * D4 + d4];
            float4 p1 = p4[(size_t)(t + 2) * D4 + d4];
            float4 p2 = p4[(size_t)(t + 4) * D4 + d4];
            float4 p3 = p4[(size_t)(t + 6) * D4 + d4];
            float4 q0 = q4[(size_t)(t    ) * D4 + d4];
            float4 q1 = q4[(size_t)(t + 2) * D4 + d4];
            float4 q2 = q4[(size_t)(t + 4) * D4 + d4];
            float4 q3 = q4[(size_t)(t + 6) * D4 + d4];

            float dx, dy, dz, dw;
            dx = p0.x - q0.x; dy = p0.y - q0.y; dz = p0.z - q0.z; dw = p0.w - q0.w;
            sdx += dx; sdy += dy; sdz += dz; sdw += dw;
            wl += smooth_l1(dx) + smooth_l1(dy) + smooth_l1(dz) + smooth_l1(dw);
            dx = p1.x - q1.x; dy = p1.y - q1.y; dz = p1.z - q1.z; dw = p1.w - q1.w;
            sdx += dx; sdy += dy; sdz += dz; sdw += dw;
            wl += smooth_l1(dx) + smooth_l1(dy) + smooth_l1(dz) + smooth_l1(dw);
            dx = p2.x - q2.x; dy = p2.y - q2.y; dz = p2.z - q2.z; dw = p2.w - q2.w;
            sdx += dx; sdy += dy; sdz += dz; sdw += dw;
            wl += smooth_l1(dx) + smooth_l1(dy) + smooth_l1(dz) + smooth_l1(dw);
            dx = p3.x - q3.x; dy = p3.y - q3.y; dz = p3.z - q3.z; dw = p3.w - q3.w;
            sdx += dx; sdy += dy; sdz += dz; sdw += dw;
            wl += smooth_l1(dx) + smooth_l1(dy) + smooth_l1(dz) + smooth_l1(dw);
        }
        for (; t < tend; t += 2) {
            float4 p = p4[(size_t)t * D4 + d4];
            float4 q = q4[(size_t)t * D4 + d4];
            float dx = p.x - q.x, dy = p.y - q.y, dz = p.z - q.z, dw = p.w - q.w;
            sdx += dx; sdy += dy; sdz += dz; sdw += dw;
            wl += smooth_l1(dx) + smooth_l1(dy) + smooth_l1(dz) + smooth_l1(dw);
        }

        // combine the two t-halves in shared, then one set of atomics
        __shared__ float s_half[D4 * 4];
        if (th == 1) {
            s_half[d4 * 4 + 0] = sdx; s_half[d4 * 4 + 1] = sdy;
            s_half[d4 * 4 + 2] = sdz; s_half[d4 * 4 + 3] = sdw;
        }
        __syncthreads();
        if (th == 0) {
            const int base = b * DD + d4 * 4;
            atomicAdd(&g_sumdiff[base + 0], sdx + s_half[d4 * 4 + 0]);
            atomicAdd(&g_sumdiff[base + 1], sdy + s_half[d4 * 4 + 1]);
            atomicAdd(&g_sumdiff[base + 2], sdz + s_half[d4 * 4 + 2]);
            atomicAdd(&g_sumdiff[base + 3], sdw + s_half[d4 * 4 + 3]);
        }

        // word-loss partial: block reduce, one atomic per block
        __shared__ float s_wl[256];
        s_wl[threadIdx.x] = wl;
        __syncthreads();
#pragma unroll
        for (int s = 128; s > 0; s >>= 1) {
            if (threadIdx.x < s) s_wl[threadIdx.x] += s_wl[threadIdx.x + s];
            __syncthreads();
        }
        if (threadIdx.x == 0) atomicAdd(&g_wl, s_wl[0]);
    }

    // ticket: EVERY block participates (incl. fully-masked early exits)
    __shared__ bool s_last;
    if (threadIdx.x == 0) {
        __threadfence();                              // release partials
        unsigned old = atomicInc(&g_count, NBLK - 1); // wraps to 0 after NBLK
        s_last = (old == NBLK - 1);
    }
    __syncthreads();
    if (!s_last) return;

    // ---- last block: finalize ----
    __threadfence();                                  // acquire all partials
    const int tid = threadIdx.x;

    __shared__ float s_len[BB];
    __shared__ float s_sumlen;
    if (tid < BB) s_len[tid] = (float)lens[tid];
    __syncthreads();
    if (tid == 0) {
        float s = 0.f;
#pragma unroll
        for (int b2 = 0; b2 < BB; b2++) s += s_len[b2];
        s_sumlen = s;
    }

    float acc = 0.f;
#pragma unroll
    for (int b2 = 0; b2 < BB; b2++) {
        float inv = 1.0f / s_len[b2];
        float m0 = g_sumdiff[b2 * DD + tid]       * inv;
        float m1 = g_sumdiff[b2 * DD + tid + 256] * inv;
        acc += smooth_l1(m0) + smooth_l1(m1);
        g_sumdiff[b2 * DD + tid]       = 0.f;     // re-zero for next invocation
        g_sumdiff[b2 * DD + tid + 256] = 0.f;
    }

    __shared__ float s_red[256];
    s_red[tid] = acc;
    __syncthreads();
#pragma unroll
    for (int s = 128; s > 0; s >>= 1) {
        if (tid < s) s_red[tid] += s_red[tid + s];
        __syncthreads();
    }

    if (tid == 0) {
        float sentence = s_red[0] / (float)DD;                 // sum_b mean_d
        float word     = g_wl / (s_sumlen * (float)DD);
        out[0] = word + sentence / (float)BB;
        g_wl = 0.f;                                            // re-zero
    }
}

extern "C" void kernel_launch(void* const* d_in, const int* in_sizes, int n_in,
                              void* d_out, int out_size)
{
    const float* preds   = (const float*)d_in[0];
    const float* targets = (const float*)d_in[1];
    const int*   lens    = (const int*)d_in[2];
    float*       out     = (float*)d_out;

    fused_kernel<<<NBLK, 256>>>(preds, targets, lens, out);
}